// round 12
// baseline (speedup 1.0000x reference)
#include <cuda_runtime.h>
#include <cuda_fp16.h>
#include <cstdint>
#include <math.h>

#define N_NODES 100000
#define N_EDGES 3200000
#define F_IN    512
#define HID     128
#define N_CLS   16

typedef unsigned short u16;

// ---------------- scratch (static device globals; no allocation) ----------
__device__ int   g_cnt[N_NODES];
__device__ int   g_off[N_NODES];
__device__ int   g_cur[N_NODES];
__device__ float g_dinv[N_NODES];
__device__ int   g_total;
__device__ int   g_ccol[N_EDGES];
__device__ u16   g_bufA[(size_t)N_NODES * HID];   // GEMM1 out (h1 pre-agg)
__device__ u16   g_bufB[(size_t)N_NODES * HID];   // agg1 out
__device__ u16   g_bufC[(size_t)N_NODES * HID];   // GEMM2 out
__device__ u16   g_w1h[HID * F_IN];               // fp16 W, [n][k]
__device__ u16   g_w2h[HID * HID];

// ---------------- helpers ---------------------------------------------------
__device__ __forceinline__ uint32_t smem_to_u32(const void* p) {
    uint32_t a;
    asm("{ .reg .u64 t; cvta.to.shared.u64 t, %1; cvt.u32.u64 %0, t; }"
        : "=r"(a) : "l"(p));
    return a;
}

#define LDSM4(r0, r1, r2, r3, addr)                                        \
    asm volatile("ldmatrix.sync.aligned.m8n8.x4.shared.b16 {%0,%1,%2,%3}, [%4];" \
                 : "=r"(r0), "=r"(r1), "=r"(r2), "=r"(r3) : "r"(addr))

#define MMA_F16(d, a, b)                                                   \
    asm volatile("mma.sync.aligned.m16n8k16.row.col.f32.f16.f16.f32 "      \
                 "{%0,%1,%2,%3}, {%4,%5,%6,%7}, {%8,%9}, {%0,%1,%2,%3};"   \
                 : "+f"((d)[0]), "+f"((d)[1]), "+f"((d)[2]), "+f"((d)[3])  \
                 : "r"((a)[0]), "r"((a)[1]), "r"((a)[2]), "r"((a)[3]),     \
                   "r"((b)[0]), "r"((b)[1]))

// ---------------- CSR construction ----------------------------------------
__global__ void zero_kernel(int n) {
    int i = blockIdx.x * blockDim.x + threadIdx.x;
    if (i < n) { g_cnt[i] = 0; g_cur[i] = 0; }
    if (i == 0) g_total = 0;
}

__global__ void count_kernel(const int* __restrict__ rows, int E) {
    int e = blockIdx.x * blockDim.x + threadIdx.x;
    if (e < E) atomicAdd(&g_cnt[rows[e]], 1);
}

// offsets + dinv fused
__global__ void offsets_kernel(int n, float fill) {
    __shared__ int s[1024];
    __shared__ int base;
    int t = threadIdx.x;
    int i = blockIdx.x * 1024 + t;
    int v = (i < n) ? g_cnt[i] : 0;
    if (i < n) g_dinv[i] = rsqrtf((float)v + fill);
    s[t] = v;
    __syncthreads();
    for (int d = 1; d < 1024; d <<= 1) {
        int u = (t >= d) ? s[t - d] : 0;
        __syncthreads();
        s[t] += u;
        __syncthreads();
    }
    if (t == 1023) base = atomicAdd(&g_total, s[1023]);
    __syncthreads();
    if (i < n) g_off[i] = base + s[t] - v;
}

__global__ void fill_kernel(const int* __restrict__ rows,
                            const int* __restrict__ cols, int E) {
    int e = blockIdx.x * blockDim.x + threadIdx.x;
    if (e < E) {
        int r = rows[e];
        int p = g_off[r] + atomicAdd(&g_cur[r], 1);
        g_ccol[p] = cols[e];
    }
}

// ---------------- W prep: transpose + fp16 ---------------------------------
__global__ void wprep_kernel(const float* __restrict__ W1,
                             const float* __restrict__ W2) {
    int i = blockIdx.x * blockDim.x + threadIdx.x;
    if (i < HID * F_IN) {
        int n = i / F_IN, k = i % F_IN;
        __half h = __float2half_rn(W1[k * HID + n]);
        g_w1h[i] = *reinterpret_cast<u16*>(&h);
    }
    int j = i - HID * F_IN;
    if (j >= 0 && j < HID * HID) {
        int n = j / HID, k = j % HID;
        __half h = __float2half_rn(W2[k * HID + n]);
        g_w2h[j] = *reinterpret_cast<u16*>(&h);
    }
}

// ---------------- HMMA fp16 GEMM (unchanged from R8 WIN) -------------------
#define BM   128
#define KCC  32
#define PADK 40
#define SMB  10240

__device__ __forceinline__ uint32_t qaddr(uint32_t base, int row0, int kb) {
    int L = threadIdx.x & 31;
    int r = row0 + (L & 15);
    int k = kb + (L >> 4) * 8;
    return base + (uint32_t)(r * (PADK * 2) + k * 2);
}

template <bool CVT>
__global__ void __launch_bounds__(256, 2)
mmagemm_kernel(const void* __restrict__ Ap,
               const u16* __restrict__ B,
               u16* __restrict__ C, int M, int K) {
    extern __shared__ __align__(16) char sm[];
    const float* Af = (const float*)Ap;
    const u16*   Ax = (const u16*)Ap;

    int tid  = threadIdx.x;
    int wid  = tid >> 5;
    int lane = tid & 31;
    int wr   = wid & 3;
    int wc   = wid >> 2;
    int m0   = blockIdx.x * BM;

    uint32_t sb = smem_to_u32(sm);
    float acc[2][8][4];
#pragma unroll
    for (int mt = 0; mt < 2; mt++)
#pragma unroll
        for (int nt = 0; nt < 8; nt++)
#pragma unroll
            for (int e = 0; e < 4; e++) acc[mt][nt][e] = 0.f;

    int arf = tid >> 3, aqf = tid & 7;
    int r16 = tid >> 2, q16 = tid & 3;

    float4 pa[4];
    uint4  paH[2], pbv[2];

    if (CVT) {
#pragma unroll
        for (int i = 0; i < 4; i++) {
            int r = arf + i * 32;
            pa[i] = make_float4(0.f, 0.f, 0.f, 0.f);
            if (m0 + r < M)
                pa[i] = *(const float4*)&Af[(size_t)(m0 + r) * K + aqf * 4];
        }
    } else {
#pragma unroll
        for (int i = 0; i < 2; i++) {
            int r = r16 + i * 64;
            paH[i] = make_uint4(0, 0, 0, 0);
            if (m0 + r < M)
                paH[i] = *(const uint4*)&Ax[(size_t)(m0 + r) * K + q16 * 8];
        }
    }
#pragma unroll
    for (int i = 0; i < 2; i++)
        pbv[i] = *(const uint4*)&B[(size_t)(r16 + i * 64) * K + q16 * 8];
    {
        u16* BsP = (u16*)(sm);
        u16* AsP = (u16*)(sm + 2 * SMB);
#pragma unroll
        for (int i = 0; i < 2; i++)
            *(uint4*)&BsP[(r16 + i * 64) * PADK + q16 * 8] = pbv[i];
        if (CVT) {
#pragma unroll
            for (int i = 0; i < 4; i++) {
                __half2 h0 = __floats2half2_rn(pa[i].x, pa[i].y);
                __half2 h1 = __floats2half2_rn(pa[i].z, pa[i].w);
                *(uint2*)&AsP[(arf + i * 32) * PADK + aqf * 4] =
                    make_uint2(*(unsigned*)&h0, *(unsigned*)&h1);
            }
        } else {
#pragma unroll
            for (int i = 0; i < 2; i++)
                *(uint4*)&AsP[(r16 + i * 64) * PADK + q16 * 8] = paH[i];
        }
    }
    __syncthreads();

    int nc = K / KCC;
    for (int c = 0; c < nc; c++) {
        int s = c & 1;
        if (c + 1 < nc) {
            int k0 = (c + 1) * KCC;
            if (CVT) {
#pragma unroll
                for (int i = 0; i < 4; i++) {
                    int r = arf + i * 32;
                    pa[i] = make_float4(0.f, 0.f, 0.f, 0.f);
                    if (m0 + r < M)
                        pa[i] = *(const float4*)&Af[(size_t)(m0 + r) * K + k0 + aqf * 4];
                }
            } else {
#pragma unroll
                for (int i = 0; i < 2; i++) {
                    int r = r16 + i * 64;
                    paH[i] = make_uint4(0, 0, 0, 0);
                    if (m0 + r < M)
                        paH[i] = *(const uint4*)&Ax[(size_t)(m0 + r) * K + k0 + q16 * 8];
                }
            }
#pragma unroll
            for (int i = 0; i < 2; i++)
                pbv[i] = *(const uint4*)&B[(size_t)(r16 + i * 64) * K + k0 + q16 * 8];
        }

        uint32_t bs_base = sb + s * SMB;
        uint32_t as_base = sb + 2 * SMB + s * SMB;
#pragma unroll
        for (int ks = 0; ks < KCC; ks += 16) {
            uint32_t bf[8][2];
#pragma unroll
            for (int g = 0; g < 4; g++) {
                uint32_t r0, r1, r2, r3;
                LDSM4(r0, r1, r2, r3, qaddr(bs_base, wc * 64 + g * 16, ks));
                bf[g * 2][0] = r0; bf[g * 2][1] = r2;
                bf[g * 2 + 1][0] = r1; bf[g * 2 + 1][1] = r3;
            }
            uint32_t ah[2][4];
#pragma unroll
            for (int mt = 0; mt < 2; mt++)
                LDSM4(ah[mt][0], ah[mt][1], ah[mt][2], ah[mt][3],
                      qaddr(as_base, wr * 32 + mt * 16, ks));
#pragma unroll
            for (int mt = 0; mt < 2; mt++)
#pragma unroll
                for (int nt = 0; nt < 8; nt++)
                    MMA_F16(acc[mt][nt], ah[mt], bf[nt]);
        }

        if (c + 1 < nc) {
            int s2 = 1 - s;
            u16* BsP = (u16*)(sm + s2 * SMB);
            u16* AsP = (u16*)(sm + 2 * SMB + s2 * SMB);
#pragma unroll
            for (int i = 0; i < 2; i++)
                *(uint4*)&BsP[(r16 + i * 64) * PADK + q16 * 8] = pbv[i];
            if (CVT) {
#pragma unroll
                for (int i = 0; i < 4; i++) {
                    __half2 h0 = __floats2half2_rn(pa[i].x, pa[i].y);
                    __half2 h1 = __floats2half2_rn(pa[i].z, pa[i].w);
                    *(uint2*)&AsP[(arf + i * 32) * PADK + aqf * 4] =
                        make_uint2(*(unsigned*)&h0, *(unsigned*)&h1);
                }
            } else {
#pragma unroll
                for (int i = 0; i < 2; i++)
                    *(uint4*)&AsP[(r16 + i * 64) * PADK + q16 * 8] = paH[i];
            }
        }
        __syncthreads();
    }

    int rbase = m0 + wr * 32 + (lane >> 2);
    int cbase = wc * 64 + (lane & 3) * 2;
#pragma unroll
    for (int mt = 0; mt < 2; mt++)
#pragma unroll
        for (int nt = 0; nt < 8; nt++) {
            int r = rbase + mt * 16;
            int cc = cbase + nt * 8;
            if (r < M) {
                __half2 v = __floats2half2_rn(acc[mt][nt][0], acc[mt][nt][1]);
                *(unsigned*)&C[(size_t)r * 128 + cc] = *reinterpret_cast<unsigned*>(&v);
            }
            if (r + 8 < M) {
                __half2 v = __floats2half2_rn(acc[mt][nt][2], acc[mt][nt][3]);
                *(unsigned*)&C[(size_t)(r + 8) * 128 + cc] = *reinterpret_cast<unsigned*>(&v);
            }
        }
}

// ---------------- aggregation: 2 rows per warp, LDG.128 gathers ------------
// lanes 0-15 -> row a, lanes 16-31 -> row b; each lane owns 8 features (uint4)
__device__ __forceinline__ void gacc8(float* a, float w, uint4 raw) {
    float2 f0 = __half22float2(*reinterpret_cast<__half2*>(&raw.x));
    float2 f1 = __half22float2(*reinterpret_cast<__half2*>(&raw.y));
    float2 f2 = __half22float2(*reinterpret_cast<__half2*>(&raw.z));
    float2 f3 = __half22float2(*reinterpret_cast<__half2*>(&raw.w));
    a[0] += w * f0.x; a[1] += w * f0.y;
    a[2] += w * f1.x; a[3] += w * f1.y;
    a[4] += w * f2.x; a[5] += w * f2.y;
    a[6] += w * f3.x; a[7] += w * f3.y;
}

__device__ __forceinline__ void agg_body2(const uint4* hv, int row, bool active,
                                          int lp, float fill, float* acc) {
    int rsafe = active ? row : 0;
    float di = active ? g_dinv[rsafe] : 0.f;
    float ws = fill * di * di;
#pragma unroll
    for (int e = 0; e < 8; e++) acc[e] = 0.f;
    gacc8(acc, ws, hv[(size_t)rsafe * 16 + lp]);

    int s = g_off[rsafe];
    int c = active ? g_cnt[rsafe] : 0;
    int cO = __shfl_xor_sync(0xffffffffu, c, 16);
    int cm = max(c, cO);
    for (int j = 0; j < cm; j += 8) {
        int cols[8];
        float w[8];
#pragma unroll
        for (int q = 0; q < 8; q++) {
            bool act = (j + q) < c;
            cols[q] = act ? __ldg(&g_ccol[s + j + q]) : rsafe;
            w[q]    = act ? di * __ldg(&g_dinv[cols[q]]) : 0.f;
        }
        uint4 u[8];
#pragma unroll
        for (int q = 0; q < 8; q++) u[q] = hv[(size_t)cols[q] * 16 + lp];
#pragma unroll
        for (int q = 0; q < 8; q++) gacc8(acc, w[q], u[q]);
    }
}

// layer-1 aggregation over rows [r0, r1): out = relu(Â h)
__global__ void agg_relu_kernel(const u16* __restrict__ h,
                                u16* __restrict__ out,
                                int r0, int r1, float fill) {
    int wp   = (blockIdx.x * blockDim.x + threadIdx.x) >> 5;
    int lane = threadIdx.x & 31;
    int half = lane >> 4, lp = lane & 15;
    int row  = r0 + wp * 2 + half;
    if (r0 + wp * 2 >= r1) return;
    bool active = row < r1;

    float acc[8];
    agg_body2((const uint4*)h, row, active, lp, fill, acc);
    if (active) {
        __half2 o0 = __floats2half2_rn(fmaxf(acc[0], 0.f), fmaxf(acc[1], 0.f));
        __half2 o1 = __floats2half2_rn(fmaxf(acc[2], 0.f), fmaxf(acc[3], 0.f));
        __half2 o2 = __floats2half2_rn(fmaxf(acc[4], 0.f), fmaxf(acc[5], 0.f));
        __half2 o3 = __floats2half2_rn(fmaxf(acc[6], 0.f), fmaxf(acc[7], 0.f));
        uint4 o = make_uint4(*(unsigned*)&o0, *(unsigned*)&o1,
                             *(unsigned*)&o2, *(unsigned*)&o3);
        ((uint4*)out)[(size_t)row * 16 + lp] = o;
    }
}

// layer-2 aggregation fused with classifier
__global__ void agg_cls_kernel(const u16* __restrict__ h,
                               const float* __restrict__ W3,
                               const float* __restrict__ b3,
                               float* __restrict__ out, int n, float fill) {
    __shared__ float sW[N_CLS * HID];
    __shared__ float sb[N_CLS];
    for (int i = threadIdx.x; i < N_CLS * HID; i += blockDim.x) sW[i] = W3[i];
    if (threadIdx.x < N_CLS) sb[threadIdx.x] = b3[threadIdx.x];
    __syncthreads();

    int wp   = (blockIdx.x * blockDim.x + threadIdx.x) >> 5;
    int lane = threadIdx.x & 31;
    int half = lane >> 4, lp = lane & 15;
    int row  = wp * 2 + half;
    if (wp * 2 >= n) return;
    bool active = row < n;

    float acc[8];
    agg_body2((const uint4*)h, row, active, lp, fill, acc);

#pragma unroll
    for (int cc = 0; cc < N_CLS; cc++) {
        const float* w = &sW[cc * 128 + lp * 8];
        float p = acc[0] * w[0] + acc[1] * w[1] + acc[2] * w[2] + acc[3] * w[3]
                + acc[4] * w[4] + acc[5] * w[5] + acc[6] * w[6] + acc[7] * w[7];
        p += __shfl_xor_sync(0xffffffffu, p, 8);
        p += __shfl_xor_sync(0xffffffffu, p, 4);
        p += __shfl_xor_sync(0xffffffffu, p, 2);
        p += __shfl_xor_sync(0xffffffffu, p, 1);
        if (lp == 0 && active) out[(size_t)row * N_CLS + cc] = p + sb[cc];
    }
}

// ---------------- launch ---------------------------------------------------
extern "C" void kernel_launch(void* const* d_in, const int* in_sizes, int n_in,
                              void* d_out, int out_size) {
    const float* x  = (const float*)d_in[0];
    const int*   ei = (const int*)d_in[1];
    const float* W1 = (const float*)d_in[2];
    const float* W2 = (const float*)d_in[3];
    const float* W3 = (const float*)d_in[4];
    const float* b3 = (const float*)d_in[5];
    float* out = (float*)d_out;

    const int E = in_sizes[1] / 2;
    const int N = in_sizes[0] / F_IN;
    const int* rows = ei;
    const int* cols = ei + E;
    const float fill = truncf(log2f((float)E / (float)N));

    u16 *bufA, *bufB, *bufC;
    cudaGetSymbolAddress((void**)&bufA, g_bufA);
    cudaGetSymbolAddress((void**)&bufB, g_bufB);
    cudaGetSymbolAddress((void**)&bufC, g_bufC);
    u16 *w1h, *w2h;
    cudaGetSymbolAddress((void**)&w1h, g_w1h);
    cudaGetSymbolAddress((void**)&w2h, g_w2h);

    cudaFuncSetAttribute(mmagemm_kernel<true>,
                         cudaFuncAttributeMaxDynamicSharedMemorySize, 4 * SMB);
    cudaFuncSetAttribute(mmagemm_kernel<false>,
                         cudaFuncAttributeMaxDynamicSharedMemorySize, 4 * SMB);

    const int T = 256;
    const int WTOT = HID * F_IN + HID * HID;
    const int GB = (N + BM - 1) / BM;

    cudaStream_t s2;
    cudaStreamCreateWithFlags(&s2, cudaStreamNonBlocking);
    cudaEvent_t eFork, eJoin, eC[4], eJoin2;
    cudaEventCreateWithFlags(&eFork, cudaEventDisableTiming);
    cudaEventCreateWithFlags(&eJoin, cudaEventDisableTiming);
    cudaEventCreateWithFlags(&eJoin2, cudaEventDisableTiming);
    for (int i = 0; i < 4; i++)
        cudaEventCreateWithFlags(&eC[i], cudaEventDisableTiming);

    // ---- fork: CSR build on side stream, overlaps wprep + GEMM1 ----
    cudaEventRecord(eFork, 0);
    cudaStreamWaitEvent(s2, eFork, 0);

    zero_kernel<<<(N + T - 1) / T, T, 0, s2>>>(N);
    count_kernel<<<(E + T - 1) / T, T, 0, s2>>>(rows, E);
    offsets_kernel<<<(N + 1023) / 1024, 1024, 0, s2>>>(N, fill);
    fill_kernel<<<(E + T - 1) / T, T, 0, s2>>>(rows, cols, E);
    cudaEventRecord(eJoin, s2);

    wprep_kernel<<<(WTOT + T - 1) / T, T>>>(W1, W2);
    mmagemm_kernel<true><<<GB, 256, 4 * SMB>>>(x, w1h, bufA, N, F_IN);

    // ---- join CSR, then agg1 in 4 chunks pipelined with GEMM2 chunks ----
    // NOTE: agg1 gathers from bufA (all rows) -> GEMM2 must NOT write bufA.
    // Chain: bufA --agg1--> bufB --gemm2--> bufC --agg_cls--> out
    cudaStreamWaitEvent(0, eJoin, 0);

    const int chunk_rows = ((GB + 3) / 4) * BM;   // multiple of BM
    for (int i = 0; i < 4; i++) {
        int r0 = i * chunk_rows;
        if (r0 >= N) break;
        int r1 = min(r0 + chunk_rows, N);
        int warps = (r1 - r0 + 1) / 2;
        agg_relu_kernel<<<(warps * 32 + T - 1) / T, T>>>(bufA, bufB, r0, r1, fill);
        cudaEventRecord(eC[i], 0);
        cudaStreamWaitEvent(s2, eC[i], 0);
        int mb = (r1 - r0 + BM - 1) / BM;
        mmagemm_kernel<false><<<mb, 256, 4 * SMB, s2>>>(
            bufB + (size_t)r0 * 128, w2h, bufC + (size_t)r0 * 128, r1 - r0, HID);
    }
    cudaEventRecord(eJoin2, s2);
    cudaStreamWaitEvent(0, eJoin2, 0);

    // ---- final aggregation + classifier ----
    {
        int warps = (N + 1) / 2;
        agg_cls_kernel<<<(warps * 32 + T - 1) / T, T>>>(bufC, W3, b3, out, N, fill);
    }

    cudaEventDestroy(eFork);
    cudaEventDestroy(eJoin);
    cudaEventDestroy(eJoin2);
    for (int i = 0; i < 4; i++) cudaEventDestroy(eC[i]);
    cudaStreamDestroy(s2);
}

// round 13
// speedup vs baseline: 1.0609x; 1.0609x over previous
#include <cuda_runtime.h>
#include <cuda_fp16.h>
#include <cstdint>
#include <math.h>

#define N_NODES 100000
#define N_EDGES 3200000
#define F_IN    512
#define HID     128
#define N_CLS   16

typedef unsigned short u16;

// ---------------- scratch (static device globals; no allocation) ----------
__device__ int   g_cnt[N_NODES];
__device__ int   g_off[N_NODES];
__device__ int   g_cur[N_NODES];
__device__ float g_dinv[N_NODES];
__device__ int   g_total;
__device__ int   g_ccol[N_EDGES];
__device__ u16   g_bufA[(size_t)N_NODES * HID];   // GEMM1 out (h1 pre-agg, fp16)
__device__ float g_bufG[(size_t)N_NODES * N_CLS]; // g = relu(Â h1) Q  (fp32)
__device__ u16   g_w1h[HID * F_IN];               // fp16 W1, [n][k]
__device__ float g_Q[HID * N_CLS];                // Q = W2 @ W3^T (fp32)

// ---------------- helpers ---------------------------------------------------
__device__ __forceinline__ uint32_t smem_to_u32(const void* p) {
    uint32_t a;
    asm("{ .reg .u64 t; cvta.to.shared.u64 t, %1; cvt.u32.u64 %0, t; }"
        : "=r"(a) : "l"(p));
    return a;
}

#define LDSM4(r0, r1, r2, r3, addr)                                        \
    asm volatile("ldmatrix.sync.aligned.m8n8.x4.shared.b16 {%0,%1,%2,%3}, [%4];" \
                 : "=r"(r0), "=r"(r1), "=r"(r2), "=r"(r3) : "r"(addr))

#define MMA_F16(d, a, b)                                                   \
    asm volatile("mma.sync.aligned.m16n8k16.row.col.f32.f16.f16.f32 "      \
                 "{%0,%1,%2,%3}, {%4,%5,%6,%7}, {%8,%9}, {%0,%1,%2,%3};"   \
                 : "+f"((d)[0]), "+f"((d)[1]), "+f"((d)[2]), "+f"((d)[3])  \
                 : "r"((a)[0]), "r"((a)[1]), "r"((a)[2]), "r"((a)[3]),     \
                   "r"((b)[0]), "r"((b)[1]))

// ---------------- CSR construction ----------------------------------------
__global__ void zero_kernel(int n) {
    int i = blockIdx.x * blockDim.x + threadIdx.x;
    if (i < n) { g_cnt[i] = 0; g_cur[i] = 0; }
    if (i == 0) g_total = 0;
}

__global__ void count_kernel(const int* __restrict__ rows, int E) {
    int e = blockIdx.x * blockDim.x + threadIdx.x;
    if (e < E) atomicAdd(&g_cnt[rows[e]], 1);
}

__global__ void offsets_kernel(int n, float fill) {
    __shared__ int s[1024];
    __shared__ int base;
    int t = threadIdx.x;
    int i = blockIdx.x * 1024 + t;
    int v = (i < n) ? g_cnt[i] : 0;
    if (i < n) g_dinv[i] = rsqrtf((float)v + fill);
    s[t] = v;
    __syncthreads();
    for (int d = 1; d < 1024; d <<= 1) {
        int u = (t >= d) ? s[t - d] : 0;
        __syncthreads();
        s[t] += u;
        __syncthreads();
    }
    if (t == 1023) base = atomicAdd(&g_total, s[1023]);
    __syncthreads();
    if (i < n) g_off[i] = base + s[t] - v;
}

__global__ void fill_kernel(const int* __restrict__ rows,
                            const int* __restrict__ cols, int E) {
    int e = blockIdx.x * blockDim.x + threadIdx.x;
    if (e < E) {
        int r = rows[e];
        int p = g_off[r] + atomicAdd(&g_cur[r], 1);
        g_ccol[p] = cols[e];
    }
}

// ---------------- W prep: W1 -> fp16 [n][k];  Q = W2 @ W3^T (fp32) ---------
__global__ void wprep_kernel(const float* __restrict__ W1) {
    int i = blockIdx.x * blockDim.x + threadIdx.x;
    if (i < HID * F_IN) {
        int n = i / F_IN, k = i % F_IN;
        __half h = __float2half_rn(W1[k * HID + n]);
        g_w1h[i] = *reinterpret_cast<u16*>(&h);
    }
}

__global__ void qprep_kernel(const float* __restrict__ W2,
                             const float* __restrict__ W3) {
    int i = blockIdx.x * blockDim.x + threadIdx.x;   // i = k*N_CLS + c
    if (i < HID * N_CLS) {
        int k = i / N_CLS, c = i % N_CLS;
        float s = 0.f;
#pragma unroll 8
        for (int j = 0; j < HID; j++)
            s += W2[k * HID + j] * W3[c * HID + j];
        g_Q[k * N_CLS + c] = s;
    }
}

// ---------------- HMMA fp16 GEMM (unchanged from R8 WIN; CVT path only) ----
#define BM   128
#define KCC  32
#define PADK 40
#define SMB  10240

__device__ __forceinline__ uint32_t qaddr(uint32_t base, int row0, int kb) {
    int L = threadIdx.x & 31;
    int r = row0 + (L & 15);
    int k = kb + (L >> 4) * 8;
    return base + (uint32_t)(r * (PADK * 2) + k * 2);
}

__global__ void __launch_bounds__(256, 2)
mmagemm_kernel(const float* __restrict__ Af,
               const u16* __restrict__ B,
               u16* __restrict__ C, int M, int K) {
    extern __shared__ __align__(16) char sm[];

    int tid  = threadIdx.x;
    int wid  = tid >> 5;
    int lane = tid & 31;
    int wr   = wid & 3;
    int wc   = wid >> 2;
    int m0   = blockIdx.x * BM;

    uint32_t sb = smem_to_u32(sm);
    float acc[2][8][4];
#pragma unroll
    for (int mt = 0; mt < 2; mt++)
#pragma unroll
        for (int nt = 0; nt < 8; nt++)
#pragma unroll
            for (int e = 0; e < 4; e++) acc[mt][nt][e] = 0.f;

    int arf = tid >> 3, aqf = tid & 7;
    int r16 = tid >> 2, q16 = tid & 3;

    float4 pa[4];
    uint4  pbv[2];

#pragma unroll
    for (int i = 0; i < 4; i++) {
        int r = arf + i * 32;
        pa[i] = make_float4(0.f, 0.f, 0.f, 0.f);
        if (m0 + r < M)
            pa[i] = *(const float4*)&Af[(size_t)(m0 + r) * K + aqf * 4];
    }
#pragma unroll
    for (int i = 0; i < 2; i++)
        pbv[i] = *(const uint4*)&B[(size_t)(r16 + i * 64) * K + q16 * 8];
    {
        u16* BsP = (u16*)(sm);
        u16* AsP = (u16*)(sm + 2 * SMB);
#pragma unroll
        for (int i = 0; i < 2; i++)
            *(uint4*)&BsP[(r16 + i * 64) * PADK + q16 * 8] = pbv[i];
#pragma unroll
        for (int i = 0; i < 4; i++) {
            __half2 h0 = __floats2half2_rn(pa[i].x, pa[i].y);
            __half2 h1 = __floats2half2_rn(pa[i].z, pa[i].w);
            *(uint2*)&AsP[(arf + i * 32) * PADK + aqf * 4] =
                make_uint2(*(unsigned*)&h0, *(unsigned*)&h1);
        }
    }
    __syncthreads();

    int nc = K / KCC;
    for (int c = 0; c < nc; c++) {
        int s = c & 1;
        if (c + 1 < nc) {
            int k0 = (c + 1) * KCC;
#pragma unroll
            for (int i = 0; i < 4; i++) {
                int r = arf + i * 32;
                pa[i] = make_float4(0.f, 0.f, 0.f, 0.f);
                if (m0 + r < M)
                    pa[i] = *(const float4*)&Af[(size_t)(m0 + r) * K + k0 + aqf * 4];
            }
#pragma unroll
            for (int i = 0; i < 2; i++)
                pbv[i] = *(const uint4*)&B[(size_t)(r16 + i * 64) * K + k0 + q16 * 8];
        }

        uint32_t bs_base = sb + s * SMB;
        uint32_t as_base = sb + 2 * SMB + s * SMB;
#pragma unroll
        for (int ks = 0; ks < KCC; ks += 16) {
            uint32_t bf[8][2];
#pragma unroll
            for (int g = 0; g < 4; g++) {
                uint32_t r0, r1, r2, r3;
                LDSM4(r0, r1, r2, r3, qaddr(bs_base, wc * 64 + g * 16, ks));
                bf[g * 2][0] = r0; bf[g * 2][1] = r2;
                bf[g * 2 + 1][0] = r1; bf[g * 2 + 1][1] = r3;
            }
            uint32_t ah[2][4];
#pragma unroll
            for (int mt = 0; mt < 2; mt++)
                LDSM4(ah[mt][0], ah[mt][1], ah[mt][2], ah[mt][3],
                      qaddr(as_base, wr * 32 + mt * 16, ks));
#pragma unroll
            for (int mt = 0; mt < 2; mt++)
#pragma unroll
                for (int nt = 0; nt < 8; nt++)
                    MMA_F16(acc[mt][nt], ah[mt], bf[nt]);
        }

        if (c + 1 < nc) {
            int s2 = 1 - s;
            u16* BsP = (u16*)(sm + s2 * SMB);
            u16* AsP = (u16*)(sm + 2 * SMB + s2 * SMB);
#pragma unroll
            for (int i = 0; i < 2; i++)
                *(uint4*)&BsP[(r16 + i * 64) * PADK + q16 * 8] = pbv[i];
#pragma unroll
            for (int i = 0; i < 4; i++) {
                __half2 h0 = __floats2half2_rn(pa[i].x, pa[i].y);
                __half2 h1 = __floats2half2_rn(pa[i].z, pa[i].w);
                *(uint2*)&AsP[(arf + i * 32) * PADK + aqf * 4] =
                    make_uint2(*(unsigned*)&h0, *(unsigned*)&h1);
            }
        }
        __syncthreads();
    }

    int rbase = m0 + wr * 32 + (lane >> 2);
    int cbase = wc * 64 + (lane & 3) * 2;
#pragma unroll
    for (int mt = 0; mt < 2; mt++)
#pragma unroll
        for (int nt = 0; nt < 8; nt++) {
            int r = rbase + mt * 16;
            int cc = cbase + nt * 8;
            if (r < M) {
                __half2 v = __floats2half2_rn(acc[mt][nt][0], acc[mt][nt][1]);
                *(unsigned*)&C[(size_t)r * 128 + cc] = *reinterpret_cast<unsigned*>(&v);
            }
            if (r + 8 < M) {
                __half2 v = __floats2half2_rn(acc[mt][nt][2], acc[mt][nt][3]);
                *(unsigned*)&C[(size_t)(r + 8) * 128 + cc] = *reinterpret_cast<unsigned*>(&v);
            }
        }
}

// ---------------- agg1 + Q epilogue ----------------------------------------
// a = relu(Â h1)[row]  (fp32, warp-resident) ; g[row] = a @ Q  (N_CLS fp32)
__device__ __forceinline__ void gacc(float4& acc, float w, uint2 raw) {
    float2 f0 = __half22float2(*reinterpret_cast<__half2*>(&raw.x));
    float2 f1 = __half22float2(*reinterpret_cast<__half2*>(&raw.y));
    acc.x += w * f0.x; acc.y += w * f0.y;
    acc.z += w * f1.x; acc.w += w * f1.y;
}

__global__ void agg1q_kernel(const u16* __restrict__ h,
                             float* __restrict__ g, int n, float fill) {
    __shared__ float sQ[N_CLS * HID];   // sQ[c*128 + k]
    for (int i = threadIdx.x; i < N_CLS * HID; i += blockDim.x) {
        int c = i / HID, k = i % HID;
        sQ[i] = g_Q[k * N_CLS + c];
    }
    __syncthreads();

    int warp = (blockIdx.x * blockDim.x + threadIdx.x) >> 5;
    int lane = threadIdx.x & 31;
    if (warp >= n) return;
    const uint2* hv = (const uint2*)h;

    float di = g_dinv[warp];
    float ws = fill * di * di;
    float4 acc = make_float4(0.f, 0.f, 0.f, 0.f);
    gacc(acc, ws, hv[(size_t)warp * 32 + lane]);

    int s = g_off[warp];
    int c = g_cnt[warp];
    int j = 0;
    for (; j + 8 <= c; j += 8) {
        int cols[8];
#pragma unroll
        for (int q = 0; q < 8; q++) cols[q] = __ldg(&g_ccol[s + j + q]);
        uint2 u[8];
#pragma unroll
        for (int q = 0; q < 8; q++) u[q] = hv[(size_t)cols[q] * 32 + lane];
        float w[8];
#pragma unroll
        for (int q = 0; q < 8; q++) w[q] = di * __ldg(&g_dinv[cols[q]]);
#pragma unroll
        for (int q = 0; q < 8; q++) gacc(acc, w[q], u[q]);
    }
    for (; j < c; j++) {
        int col = __ldg(&g_ccol[s + j]);
        float w = di * __ldg(&g_dinv[col]);
        gacc(acc, w, hv[(size_t)col * 32 + lane]);
    }
    acc.x = fmaxf(acc.x, 0.f);
    acc.y = fmaxf(acc.y, 0.f);
    acc.z = fmaxf(acc.z, 0.f);
    acc.w = fmaxf(acc.w, 0.f);

    // epilogue: g[row][cc] = sum_k a[k] * Q[k][cc]
#pragma unroll
    for (int cc = 0; cc < N_CLS; cc++) {
        float4 q = *(const float4*)&sQ[cc * 128 + lane * 4];
        float  p = acc.x * q.x + acc.y * q.y + acc.z * q.z + acc.w * q.w;
        p += __shfl_xor_sync(0xffffffffu, p, 16);
        p += __shfl_xor_sync(0xffffffffu, p, 8);
        p += __shfl_xor_sync(0xffffffffu, p, 4);
        p += __shfl_xor_sync(0xffffffffu, p, 2);
        p += __shfl_xor_sync(0xffffffffu, p, 1);
        if (lane == 0) g[(size_t)warp * N_CLS + cc] = p;
    }
}

// ---------------- agg2: out = Â g + b3  (16 features) ----------------------
// 2 rows per warp: lanes 0-15 row a, 16-31 row b; lane owns feature lp.
__global__ void agg2_kernel(const float* __restrict__ g,
                            const float* __restrict__ b3,
                            float* __restrict__ out, int n, float fill) {
    __shared__ float sb[N_CLS];
    if (threadIdx.x < N_CLS) sb[threadIdx.x] = b3[threadIdx.x];
    __syncthreads();

    int wp   = (blockIdx.x * blockDim.x + threadIdx.x) >> 5;
    int lane = threadIdx.x & 31;
    int half = lane >> 4, lp = lane & 15;
    int row  = wp * 2 + half;
    if (wp * 2 >= n) return;
    bool active = row < n;
    int rsafe = active ? row : 0;

    float di = active ? g_dinv[rsafe] : 0.f;
    float ws = fill * di * di;
    float acc = ws * g[(size_t)rsafe * N_CLS + lp];

    int s = g_off[rsafe];
    int c = active ? g_cnt[rsafe] : 0;
    int cO = __shfl_xor_sync(0xffffffffu, c, 16);
    int cm = max(c, cO);
    for (int j = 0; j < cm; j += 8) {
        int cols[8];
        float w[8];
#pragma unroll
        for (int q = 0; q < 8; q++) {
            bool act = (j + q) < c;
            cols[q] = act ? __ldg(&g_ccol[s + j + q]) : rsafe;
            w[q]    = act ? di * __ldg(&g_dinv[cols[q]]) : 0.f;
        }
#pragma unroll
        for (int q = 0; q < 8; q++)
            acc += w[q] * __ldg(&g[(size_t)cols[q] * N_CLS + lp]);
    }
    if (active) out[(size_t)row * N_CLS + lp] = acc + sb[lp];
}

// ---------------- launch ---------------------------------------------------
extern "C" void kernel_launch(void* const* d_in, const int* in_sizes, int n_in,
                              void* d_out, int out_size) {
    const float* x  = (const float*)d_in[0];
    const int*   ei = (const int*)d_in[1];
    const float* W1 = (const float*)d_in[2];
    const float* W2 = (const float*)d_in[3];
    const float* W3 = (const float*)d_in[4];
    const float* b3 = (const float*)d_in[5];
    float* out = (float*)d_out;

    const int E = in_sizes[1] / 2;
    const int N = in_sizes[0] / F_IN;
    const int* rows = ei;
    const int* cols = ei + E;
    const float fill = truncf(log2f((float)E / (float)N));

    u16* bufA;   cudaGetSymbolAddress((void**)&bufA, g_bufA);
    float* bufG; cudaGetSymbolAddress((void**)&bufG, g_bufG);
    u16* w1h;    cudaGetSymbolAddress((void**)&w1h, g_w1h);

    cudaFuncSetAttribute(mmagemm_kernel,
                         cudaFuncAttributeMaxDynamicSharedMemorySize, 4 * SMB);

    const int T = 256;
    const int GB = (N + BM - 1) / BM;

    cudaStream_t s2;
    cudaStreamCreateWithFlags(&s2, cudaStreamNonBlocking);
    cudaEvent_t eFork, eJoin;
    cudaEventCreateWithFlags(&eFork, cudaEventDisableTiming);
    cudaEventCreateWithFlags(&eJoin, cudaEventDisableTiming);

    // fork: CSR build on side stream, overlaps wprep/qprep + GEMM1
    cudaEventRecord(eFork, 0);
    cudaStreamWaitEvent(s2, eFork, 0);

    zero_kernel<<<(N + T - 1) / T, T, 0, s2>>>(N);
    count_kernel<<<(E + T - 1) / T, T, 0, s2>>>(rows, E);
    offsets_kernel<<<(N + 1023) / 1024, 1024, 0, s2>>>(N, fill);
    fill_kernel<<<(E + T - 1) / T, T, 0, s2>>>(rows, cols, E);
    cudaEventRecord(eJoin, s2);

    wprep_kernel<<<(HID * F_IN + T - 1) / T, T>>>(W1);
    qprep_kernel<<<(HID * N_CLS + T - 1) / T, T>>>(W2, W3);
    mmagemm_kernel<<<GB, 256, 4 * SMB>>>(x, w1h, bufA, N, F_IN);

    // join, then agg1 (+Q epilogue) and the 16-wide second aggregation
    cudaStreamWaitEvent(0, eJoin, 0);
    agg1q_kernel<<<(N * 32 + T - 1) / T, T>>>(bufA, bufG, N, fill);
    {
        int warps = (N + 1) / 2;
        agg2_kernel<<<(warps * 32 + T - 1) / T, T>>>(bufG, b3, out, N, fill);
    }

    cudaEventDestroy(eFork);
    cudaEventDestroy(eJoin);
    cudaStreamDestroy(s2);
}

// round 14
// speedup vs baseline: 1.0925x; 1.0297x over previous
#include <cuda_runtime.h>
#include <cuda_fp16.h>
#include <cstdint>
#include <math.h>

#define N_NODES 100000
#define N_EDGES 3200000
#define F_IN    512
#define HID     128
#define N_CLS   16

typedef unsigned short u16;

// ---------------- scratch (static device globals; no allocation) ----------
__device__ int   g_cnt[N_NODES];
__device__ int   g_off[N_NODES];
__device__ float g_dinv[N_NODES];
__device__ int   g_total;
__device__ int   g_rank[N_EDGES];                 // per-edge slot within row
__device__ int   g_ccol[N_EDGES];
__device__ u16   g_bufA[(size_t)N_NODES * HID];   // GEMM1 out (h1 pre-agg, fp16)
__device__ u16   g_bufG[(size_t)N_NODES * N_CLS]; // g = relu(Â h1) Q  (fp16)
__device__ u16   g_w1h[HID * F_IN];               // fp16 W1, [n][k]
__device__ float g_Q[HID * N_CLS];                // Q = W2 @ W3^T (fp32)

// ---------------- helpers ---------------------------------------------------
__device__ __forceinline__ uint32_t smem_to_u32(const void* p) {
    uint32_t a;
    asm("{ .reg .u64 t; cvta.to.shared.u64 t, %1; cvt.u32.u64 %0, t; }"
        : "=r"(a) : "l"(p));
    return a;
}

#define LDSM4(r0, r1, r2, r3, addr)                                        \
    asm volatile("ldmatrix.sync.aligned.m8n8.x4.shared.b16 {%0,%1,%2,%3}, [%4];" \
                 : "=r"(r0), "=r"(r1), "=r"(r2), "=r"(r3) : "r"(addr))

#define MMA_F16(d, a, b)                                                   \
    asm volatile("mma.sync.aligned.m16n8k16.row.col.f32.f16.f16.f32 "      \
                 "{%0,%1,%2,%3}, {%4,%5,%6,%7}, {%8,%9}, {%0,%1,%2,%3};"   \
                 : "+f"((d)[0]), "+f"((d)[1]), "+f"((d)[2]), "+f"((d)[3])  \
                 : "r"((a)[0]), "r"((a)[1]), "r"((a)[2]), "r"((a)[3]),     \
                   "r"((b)[0]), "r"((b)[1]))

// ---------------- CSR construction ----------------------------------------
// count + rank: rank[e] = position of edge within its row (atomic cursor)
__global__ void count_kernel(const int* __restrict__ rows, int E) {
    int e = blockIdx.x * blockDim.x + threadIdx.x;
    if (e < E) g_rank[e] = atomicAdd(&g_cnt[rows[e]], 1);
}

// offsets + dinv fused
__global__ void offsets_kernel(int n, float fill) {
    __shared__ int s[1024];
    __shared__ int base;
    int t = threadIdx.x;
    int i = blockIdx.x * 1024 + t;
    int v = (i < n) ? g_cnt[i] : 0;
    if (i < n) g_dinv[i] = rsqrtf((float)v + fill);
    s[t] = v;
    __syncthreads();
    for (int d = 1; d < 1024; d <<= 1) {
        int u = (t >= d) ? s[t - d] : 0;
        __syncthreads();
        s[t] += u;
        __syncthreads();
    }
    if (t == 1023) base = atomicAdd(&g_total, s[1023]);
    __syncthreads();
    if (i < n) g_off[i] = base + s[t] - v;
}

// atomic-free fill: pure stream read + scatter
__global__ void fill_kernel(const int* __restrict__ rows,
                            const int* __restrict__ cols, int E) {
    int e = blockIdx.x * blockDim.x + threadIdx.x;
    if (e < E)
        g_ccol[g_off[rows[e]] + g_rank[e]] = cols[e];
}

// ---------------- W prep (merged): W1 -> fp16 [n][k]; Q = W2 @ W3^T --------
__global__ void wqprep_kernel(const float* __restrict__ W1,
                              const float* __restrict__ W2,
                              const float* __restrict__ W3) {
    int i = blockIdx.x * blockDim.x + threadIdx.x;
    if (i < HID * F_IN) {
        int n = i / F_IN, k = i % F_IN;
        __half h = __float2half_rn(W1[k * HID + n]);
        g_w1h[i] = *reinterpret_cast<u16*>(&h);
    }
    int j = i - HID * F_IN;
    if (j >= 0 && j < HID * N_CLS) {
        int k = j / N_CLS, c = j % N_CLS;
        float s = 0.f;
#pragma unroll 8
        for (int q = 0; q < HID; q++)
            s += W2[k * HID + q] * W3[c * HID + q];
        g_Q[k * N_CLS + c] = s;
    }
}

// ---------------- HMMA fp16 GEMM (unchanged from R8 WIN) -------------------
#define BM   128
#define KCC  32
#define PADK 40
#define SMB  10240

__device__ __forceinline__ uint32_t qaddr(uint32_t base, int row0, int kb) {
    int L = threadIdx.x & 31;
    int r = row0 + (L & 15);
    int k = kb + (L >> 4) * 8;
    return base + (uint32_t)(r * (PADK * 2) + k * 2);
}

__global__ void __launch_bounds__(256, 2)
mmagemm_kernel(const float* __restrict__ Af,
               const u16* __restrict__ B,
               u16* __restrict__ C, int M, int K) {
    extern __shared__ __align__(16) char sm[];

    int tid  = threadIdx.x;
    int wid  = tid >> 5;
    int lane = tid & 31;
    int wr   = wid & 3;
    int wc   = wid >> 2;
    int m0   = blockIdx.x * BM;

    uint32_t sb = smem_to_u32(sm);
    float acc[2][8][4];
#pragma unroll
    for (int mt = 0; mt < 2; mt++)
#pragma unroll
        for (int nt = 0; nt < 8; nt++)
#pragma unroll
            for (int e = 0; e < 4; e++) acc[mt][nt][e] = 0.f;

    int arf = tid >> 3, aqf = tid & 7;
    int r16 = tid >> 2, q16 = tid & 3;

    float4 pa[4];
    uint4  pbv[2];

#pragma unroll
    for (int i = 0; i < 4; i++) {
        int r = arf + i * 32;
        pa[i] = make_float4(0.f, 0.f, 0.f, 0.f);
        if (m0 + r < M)
            pa[i] = *(const float4*)&Af[(size_t)(m0 + r) * K + aqf * 4];
    }
#pragma unroll
    for (int i = 0; i < 2; i++)
        pbv[i] = *(const uint4*)&B[(size_t)(r16 + i * 64) * K + q16 * 8];
    {
        u16* BsP = (u16*)(sm);
        u16* AsP = (u16*)(sm + 2 * SMB);
#pragma unroll
        for (int i = 0; i < 2; i++)
            *(uint4*)&BsP[(r16 + i * 64) * PADK + q16 * 8] = pbv[i];
#pragma unroll
        for (int i = 0; i < 4; i++) {
            __half2 h0 = __floats2half2_rn(pa[i].x, pa[i].y);
            __half2 h1 = __floats2half2_rn(pa[i].z, pa[i].w);
            *(uint2*)&AsP[(arf + i * 32) * PADK + aqf * 4] =
                make_uint2(*(unsigned*)&h0, *(unsigned*)&h1);
        }
    }
    __syncthreads();

    int nc = K / KCC;
    for (int c = 0; c < nc; c++) {
        int s = c & 1;
        if (c + 1 < nc) {
            int k0 = (c + 1) * KCC;
#pragma unroll
            for (int i = 0; i < 4; i++) {
                int r = arf + i * 32;
                pa[i] = make_float4(0.f, 0.f, 0.f, 0.f);
                if (m0 + r < M)
                    pa[i] = *(const float4*)&Af[(size_t)(m0 + r) * K + k0 + aqf * 4];
            }
#pragma unroll
            for (int i = 0; i < 2; i++)
                pbv[i] = *(const uint4*)&B[(size_t)(r16 + i * 64) * K + k0 + q16 * 8];
        }

        uint32_t bs_base = sb + s * SMB;
        uint32_t as_base = sb + 2 * SMB + s * SMB;
#pragma unroll
        for (int ks = 0; ks < KCC; ks += 16) {
            uint32_t bf[8][2];
#pragma unroll
            for (int g = 0; g < 4; g++) {
                uint32_t r0, r1, r2, r3;
                LDSM4(r0, r1, r2, r3, qaddr(bs_base, wc * 64 + g * 16, ks));
                bf[g * 2][0] = r0; bf[g * 2][1] = r2;
                bf[g * 2 + 1][0] = r1; bf[g * 2 + 1][1] = r3;
            }
            uint32_t ah[2][4];
#pragma unroll
            for (int mt = 0; mt < 2; mt++)
                LDSM4(ah[mt][0], ah[mt][1], ah[mt][2], ah[mt][3],
                      qaddr(as_base, wr * 32 + mt * 16, ks));
#pragma unroll
            for (int mt = 0; mt < 2; mt++)
#pragma unroll
                for (int nt = 0; nt < 8; nt++)
                    MMA_F16(acc[mt][nt], ah[mt], bf[nt]);
        }

        if (c + 1 < nc) {
            int s2 = 1 - s;
            u16* BsP = (u16*)(sm + s2 * SMB);
            u16* AsP = (u16*)(sm + 2 * SMB + s2 * SMB);
#pragma unroll
            for (int i = 0; i < 2; i++)
                *(uint4*)&BsP[(r16 + i * 64) * PADK + q16 * 8] = pbv[i];
#pragma unroll
            for (int i = 0; i < 4; i++) {
                __half2 h0 = __floats2half2_rn(pa[i].x, pa[i].y);
                __half2 h1 = __floats2half2_rn(pa[i].z, pa[i].w);
                *(uint2*)&AsP[(arf + i * 32) * PADK + aqf * 4] =
                    make_uint2(*(unsigned*)&h0, *(unsigned*)&h1);
            }
        }
        __syncthreads();
    }

    int rbase = m0 + wr * 32 + (lane >> 2);
    int cbase = wc * 64 + (lane & 3) * 2;
#pragma unroll
    for (int mt = 0; mt < 2; mt++)
#pragma unroll
        for (int nt = 0; nt < 8; nt++) {
            int r = rbase + mt * 16;
            int cc = cbase + nt * 8;
            if (r < M) {
                __half2 v = __floats2half2_rn(acc[mt][nt][0], acc[mt][nt][1]);
                *(unsigned*)&C[(size_t)r * 128 + cc] = *reinterpret_cast<unsigned*>(&v);
            }
            if (r + 8 < M) {
                __half2 v = __floats2half2_rn(acc[mt][nt][2], acc[mt][nt][3]);
                *(unsigned*)&C[(size_t)(r + 8) * 128 + cc] = *reinterpret_cast<unsigned*>(&v);
            }
        }
}

// ---------------- agg1 + Q epilogue ----------------------------------------
__device__ __forceinline__ void gacc(float4& acc, float w, uint2 raw) {
    float2 f0 = __half22float2(*reinterpret_cast<__half2*>(&raw.x));
    float2 f1 = __half22float2(*reinterpret_cast<__half2*>(&raw.y));
    acc.x += w * f0.x; acc.y += w * f0.y;
    acc.z += w * f1.x; acc.w += w * f1.y;
}

__global__ void agg1q_kernel(const u16* __restrict__ h,
                             u16* __restrict__ g, int n, float fill) {
    __shared__ float sQ[N_CLS * HID];   // sQ[c*128 + k]
    for (int i = threadIdx.x; i < N_CLS * HID; i += blockDim.x) {
        int c = i / HID, k = i % HID;
        sQ[i] = g_Q[k * N_CLS + c];
    }
    __syncthreads();

    int warp = (blockIdx.x * blockDim.x + threadIdx.x) >> 5;
    int lane = threadIdx.x & 31;
    if (warp >= n) return;
    const uint2* hv = (const uint2*)h;

    float di = g_dinv[warp];
    float ws = fill * di * di;
    float4 acc = make_float4(0.f, 0.f, 0.f, 0.f);
    gacc(acc, ws, hv[(size_t)warp * 32 + lane]);

    int s = g_off[warp];
    int c = g_cnt[warp];
    int j = 0;
    for (; j + 8 <= c; j += 8) {
        int cols[8];
#pragma unroll
        for (int q = 0; q < 8; q++) cols[q] = __ldg(&g_ccol[s + j + q]);
        uint2 u[8];
#pragma unroll
        for (int q = 0; q < 8; q++) u[q] = hv[(size_t)cols[q] * 32 + lane];
        float w[8];
#pragma unroll
        for (int q = 0; q < 8; q++) w[q] = di * __ldg(&g_dinv[cols[q]]);
#pragma unroll
        for (int q = 0; q < 8; q++) gacc(acc, w[q], u[q]);
    }
    for (; j < c; j++) {
        int col = __ldg(&g_ccol[s + j]);
        float w = di * __ldg(&g_dinv[col]);
        gacc(acc, w, hv[(size_t)col * 32 + lane]);
    }
    acc.x = fmaxf(acc.x, 0.f);
    acc.y = fmaxf(acc.y, 0.f);
    acc.z = fmaxf(acc.z, 0.f);
    acc.w = fmaxf(acc.w, 0.f);

    // epilogue: g[row][cc] = sum_k a[k] * Q[k][cc]  (fp16 store)
#pragma unroll
    for (int cc = 0; cc < N_CLS; cc++) {
        float4 q = *(const float4*)&sQ[cc * 128 + lane * 4];
        float  p = acc.x * q.x + acc.y * q.y + acc.z * q.z + acc.w * q.w;
        p += __shfl_xor_sync(0xffffffffu, p, 16);
        p += __shfl_xor_sync(0xffffffffu, p, 8);
        p += __shfl_xor_sync(0xffffffffu, p, 4);
        p += __shfl_xor_sync(0xffffffffu, p, 2);
        p += __shfl_xor_sync(0xffffffffu, p, 1);
        if (lane == 0) {
            __half hv16 = __float2half_rn(p);
            g[(size_t)warp * N_CLS + cc] = *reinterpret_cast<u16*>(&hv16);
        }
    }
}

// ---------------- agg2: out = Â g + b3  (16 fp16 features) -----------------
// 2 rows per warp: lanes 0-15 row a, 16-31 row b; lane owns feature lp.
__global__ void agg2_kernel(const u16* __restrict__ g,
                            const float* __restrict__ b3,
                            float* __restrict__ out, int n, float fill) {
    __shared__ float sb[N_CLS];
    if (threadIdx.x < N_CLS) sb[threadIdx.x] = b3[threadIdx.x];
    __syncthreads();

    int wp   = (blockIdx.x * blockDim.x + threadIdx.x) >> 5;
    int lane = threadIdx.x & 31;
    int half = lane >> 4, lp = lane & 15;
    int row  = wp * 2 + half;
    if (wp * 2 >= n) return;
    bool active = row < n;
    int rsafe = active ? row : 0;

    float di = active ? g_dinv[rsafe] : 0.f;
    float ws = fill * di * di;
    float acc = ws * __half2float(
        *reinterpret_cast<const __half*>(&g[(size_t)rsafe * N_CLS + lp]));

    int s = g_off[rsafe];
    int c = active ? g_cnt[rsafe] : 0;
    int cO = __shfl_xor_sync(0xffffffffu, c, 16);
    int cm = max(c, cO);
    for (int j = 0; j < cm; j += 8) {
        int cols[8];
        float w[8];
#pragma unroll
        for (int q = 0; q < 8; q++) {
            bool act = (j + q) < c;
            cols[q] = act ? __ldg(&g_ccol[s + j + q]) : rsafe;
            w[q]    = act ? di * __ldg(&g_dinv[cols[q]]) : 0.f;
        }
#pragma unroll
        for (int q = 0; q < 8; q++) {
            float gv = __half2float(*reinterpret_cast<const __half*>(
                &g[(size_t)cols[q] * N_CLS + lp]));
            acc += w[q] * gv;
        }
    }
    if (active) out[(size_t)row * N_CLS + lp] = acc + sb[lp];
}

// ---------------- launch ---------------------------------------------------
extern "C" void kernel_launch(void* const* d_in, const int* in_sizes, int n_in,
                              void* d_out, int out_size) {
    const float* x  = (const float*)d_in[0];
    const int*   ei = (const int*)d_in[1];
    const float* W1 = (const float*)d_in[2];
    const float* W2 = (const float*)d_in[3];
    const float* W3 = (const float*)d_in[4];
    const float* b3 = (const float*)d_in[5];
    float* out = (float*)d_out;

    const int E = in_sizes[1] / 2;
    const int N = in_sizes[0] / F_IN;
    const int* rows = ei;
    const int* cols = ei + E;
    const float fill = truncf(log2f((float)E / (float)N));

    u16* bufA; cudaGetSymbolAddress((void**)&bufA, g_bufA);
    u16* bufG; cudaGetSymbolAddress((void**)&bufG, g_bufG);
    u16* w1h;  cudaGetSymbolAddress((void**)&w1h, g_w1h);
    int* cntp; cudaGetSymbolAddress((void**)&cntp, g_cnt);
    int* totp; cudaGetSymbolAddress((void**)&totp, g_total);

    cudaFuncSetAttribute(mmagemm_kernel,
                         cudaFuncAttributeMaxDynamicSharedMemorySize, 4 * SMB);

    const int T = 256;
    const int GB = (N + BM - 1) / BM;

    cudaStream_t s2;
    cudaStreamCreateWithFlags(&s2, cudaStreamNonBlocking);
    cudaEvent_t eFork, eJoin;
    cudaEventCreateWithFlags(&eFork, cudaEventDisableTiming);
    cudaEventCreateWithFlags(&eJoin, cudaEventDisableTiming);

    // fork: CSR build on side stream, overlaps wqprep + GEMM1
    cudaEventRecord(eFork, 0);
    cudaStreamWaitEvent(s2, eFork, 0);

    cudaMemsetAsync(cntp, 0, N_NODES * sizeof(int), s2);
    cudaMemsetAsync(totp, 0, sizeof(int), s2);
    count_kernel<<<(E + T - 1) / T, T, 0, s2>>>(rows, E);
    offsets_kernel<<<(N + 1023) / 1024, 1024, 0, s2>>>(N, fill);
    fill_kernel<<<(E + T - 1) / T, T, 0, s2>>>(rows, cols, E);
    cudaEventRecord(eJoin, s2);

    wqprep_kernel<<<(HID * F_IN + HID * N_CLS + T - 1) / T, T>>>(W1, W2, W3);
    mmagemm_kernel<<<GB, 256, 4 * SMB>>>(x, w1h, bufA, N, F_IN);

    // join, then agg1 (+Q epilogue) and the 16-wide second aggregation
    cudaStreamWaitEvent(0, eJoin, 0);
    agg1q_kernel<<<(N * 32 + T - 1) / T, T>>>(bufA, bufG, N, fill);
    {
        int warps = (N + 1) / 2;
        agg2_kernel<<<(warps * 32 + T - 1) / T, T>>>(bufG, b3, out, N, fill);
    }

    cudaEventDestroy(eFork);
    cudaEventDestroy(eJoin);
    cudaStreamDestroy(s2);
}